// round 12
// baseline (speedup 1.0000x reference)
#include <cuda_runtime.h>

// EfConv: out[n, k*64+o] = sum_{e: dst_e=n} ef[e,k] * (node_feat[src_e] . W[o]) + b[o]
// y = X @ W^T first (side stream). Fixed-capacity buckets (128/node) -> build
// is one scatter pass; spill list guarantees correctness.
// R12: k_main splits each node across TWO warps by output-half (o in [0,32) /
// [32,64)): acc 4xu64, y 1 float/lane -> ~48 regs -> 5 CTAs/SM (40 warps).
// g_cnt reset folded into k_main; k_spill shrunk to one block.

#define MAXN 50000
#define MAXE 800000
#define NF 64
#define ED 8
#define CAP 128                  // bucket slots per node

typedef unsigned long long u64;

__device__ int   g_cnt[MAXN];        // zero at load; re-zeroed by k_main each call
__device__ int   g_nspill;           // re-zeroed by k_spill
__device__ int4  g_spill[MAXE];      // (src, eid, dst, 0) overflow edges
__device__ __align__(16) int2 g_rec[(size_t)MAXN * CAP];   // buckets
__device__ float g_y[(size_t)(MAXN + 1) * NF];    // row MAXN stays all-zero (pad target)

// ---------------- packed f32x2 helpers ----------------
__device__ __forceinline__ void ffma2(u64 &d, u64 a, u64 b) {
    asm("fma.rn.f32x2 %0, %1, %2, %0;" : "+l"(d) : "l"(a), "l"(b));
}
__device__ __forceinline__ u64 pack2(float lo, float hi) {
    u64 r;
    asm("mov.b64 %0, {%1, %2};" : "=l"(r) : "f"(lo), "f"(hi));
    return r;
}
__device__ __forceinline__ void unpack2(float &lo, float &hi, u64 v) {
    asm("mov.b64 {%0, %1}, %2;" : "=f"(lo), "=f"(hi) : "l"(v));
}

// ---------------- scatter: the ONLY build pass ----------------
__global__ void k_scatter(const int* __restrict__ src, const int* __restrict__ dst, int E) {
    int t = blockIdx.x * blockDim.x + threadIdx.x;
    if (t >= E) return;
    int d = dst[t];
    int s = src[t];
    int pos = atomicAdd(&g_cnt[d], 1);
    if (pos < CAP) {
        g_rec[(size_t)d * CAP + pos] = make_int2(s, t);
    } else {
        int sp = atomicAdd(&g_nspill, 1);
        g_spill[sp] = make_int4(s, t, d, 0);
    }
}

// ---------------- y = X @ W^T : 64 nodes/block, 4 nodes/thread ----------------
__global__ void __launch_bounds__(256) k_ygemm(const float* __restrict__ X,
                                               const float* __restrict__ W, int N) {
    __shared__ float WsT[NF * 68];
    __shared__ float xs[64][NF];
    int t = threadIdx.x;
    int base = blockIdx.x * 64;

    #pragma unroll
    for (int k = 0; k < 16; k++) {
        int idx = t + k * 256;
        int o = idx >> 6, i = idx & 63;
        WsT[i * 68 + o] = W[idx];
    }
    #pragma unroll
    for (int k = 0; k < 4; k++) {
        int idx = t + k * 256;
        int ln = idx >> 4, q = idx & 15;
        int n = base + ln;
        float4 v = (n < N) ? ((const float4*)(X + (size_t)n * NF))[q]
                           : make_float4(0.f, 0.f, 0.f, 0.f);
        ((float4*)&xs[ln][0])[q] = v;
    }
    __syncthreads();

    int o4 = (t & 15) * 4;
    int slot = t >> 4;
    float4 a0 = make_float4(0.f, 0.f, 0.f, 0.f);
    float4 a1 = a0, a2 = a0, a3 = a0;
    #pragma unroll 8
    for (int i = 0; i < NF; i++) {
        float4 w = *(const float4*)&WsT[i * 68 + o4];
        float x0 = xs[slot][i];
        float x1 = xs[slot + 16][i];
        float x2 = xs[slot + 32][i];
        float x3 = xs[slot + 48][i];
        a0.x += w.x * x0; a0.y += w.y * x0; a0.z += w.z * x0; a0.w += w.w * x0;
        a1.x += w.x * x1; a1.y += w.y * x1; a1.z += w.z * x1; a1.w += w.w * x1;
        a2.x += w.x * x2; a2.y += w.y * x2; a2.z += w.z * x2; a2.w += w.w * x2;
        a3.x += w.x * x3; a3.y += w.y * x3; a3.z += w.z * x3; a3.w += w.w * x3;
    }
    int n0 = base + slot;
    if (n0 < N)      *(float4*)(g_y + (size_t)n0 * NF + o4) = a0;
    if (n0 + 16 < N) *(float4*)(g_y + (size_t)(n0 + 16) * NF + o4) = a1;
    if (n0 + 32 < N) *(float4*)(g_y + (size_t)(n0 + 32) * NF + o4) = a2;
    if (n0 + 48 < N) *(float4*)(g_y + (size_t)(n0 + 48) * NF + o4) = a3;
}

// ---------------- main: 2 warps per node (o-halves), bucket staged privately ----------------
// acc[p] = packed (k=2p, k=2p+1) for this lane's single output feature.
__device__ __forceinline__ void edge1(u64 (&acc)[4], float4 ea, float4 eb, float yv) {
    u64 ys  = pack2(yv, yv);
    u64 e01 = pack2(ea.x, ea.y);
    u64 e23 = pack2(ea.z, ea.w);
    u64 e45 = pack2(eb.x, eb.y);
    u64 e67 = pack2(eb.z, eb.w);
    ffma2(acc[0], e01, ys);
    ffma2(acc[1], e23, ys);
    ffma2(acc[2], e45, ys);
    ffma2(acc[3], e67, ys);
}

__device__ __forceinline__ void batch8h(u64 (&acc)[4], const float* __restrict__ ef,
                                        const float* yb, int4 r01, int4 r23,
                                        int4 r45, int4 r67) {
    float y0 = yb[(size_t)r01.x * NF];
    float y1 = yb[(size_t)r01.z * NF];
    float y2 = yb[(size_t)r23.x * NF];
    float y3 = yb[(size_t)r23.z * NF];
    float y4 = yb[(size_t)r45.x * NF];
    float y5 = yb[(size_t)r45.z * NF];
    float y6 = yb[(size_t)r67.x * NF];
    float y7 = yb[(size_t)r67.z * NF];
    const float4* e0 = (const float4*)(ef + (size_t)r01.y * ED);
    const float4* e1 = (const float4*)(ef + (size_t)r01.w * ED);
    const float4* e2 = (const float4*)(ef + (size_t)r23.y * ED);
    const float4* e3 = (const float4*)(ef + (size_t)r23.w * ED);
    const float4* e4 = (const float4*)(ef + (size_t)r45.y * ED);
    const float4* e5 = (const float4*)(ef + (size_t)r45.w * ED);
    const float4* e6 = (const float4*)(ef + (size_t)r67.y * ED);
    const float4* e7 = (const float4*)(ef + (size_t)r67.w * ED);
    edge1(acc, e0[0], e0[1], y0);
    edge1(acc, e1[0], e1[1], y1);
    edge1(acc, e2[0], e2[1], y2);
    edge1(acc, e3[0], e3[1], y3);
    edge1(acc, e4[0], e4[1], y4);
    edge1(acc, e5[0], e5[1], y5);
    edge1(acc, e6[0], e6[1], y6);
    edge1(acc, e7[0], e7[1], y7);
}

__global__ void __launch_bounds__(256, 5) k_main(const float* __restrict__ ef,
                                                 const float* __restrict__ bvec,
                                                 float* __restrict__ out, int N) {
    __shared__ __align__(16) int2 srec[8][CAP];
    int wid = threadIdx.x >> 5;
    int lane = threadIdx.x & 31;
    int node = blockIdx.x * 4 + (wid >> 1);
    int half = wid & 1;                        // o in [half*32, half*32+32)
    bool live = (node < N);

    int cnt = 0;
    if (live) {
        cnt = g_cnt[node];
        if (cnt > CAP) cnt = CAP;              // overflow handled by k_spill
        const int2* bucket = g_rec + (size_t)node * CAP;
        // private staging (coalesced 256B loads)
        #pragma unroll
        for (int k = 0; k < CAP / 32; k++) {
            int idx = lane + k * 32;
            if (idx < cnt) srec[wid][idx] = bucket[idx];
        }
        int cnt8 = (cnt + 7) & ~7;
        if (lane < cnt8 - cnt) srec[wid][cnt + lane] = make_int2(N, 0);
        __syncwarp();

        u64 acc[4];
        #pragma unroll
        for (int a = 0; a < 4; a++) acc[a] = 0ull;

        const float* yb = g_y + half * 32 + lane;

        for (int j = 0; j < cnt8; j += 8) {
            const int4* rp = (const int4*)&srec[wid][j];   // broadcast LDS
            batch8h(acc, ef, yb, rp[0], rp[1], rp[2], rp[3]);
        }

        float bb = bvec[half * 32 + lane];
        float* op = out + (size_t)node * (ED * NF) + half * 32 + lane;
        #pragma unroll
        for (int p = 0; p < 4; p++) {
            float k0, k1;
            unpack2(k0, k1, acc[p]);
            op[(2 * p) * NF]     = k0 + bb;
            op[(2 * p + 1) * NF] = k1 + bb;
        }
    }

    // reset counters for the NEXT invocation (after both owning warps read them)
    __syncthreads();
    if (threadIdx.x < 4) {
        int n2 = blockIdx.x * 4 + threadIdx.x;
        if (n2 < N) g_cnt[n2] = 0;
    }
}

// ---------------- spill fixup (normally empty) + nspill reset ----------------
__global__ void k_spill(const float* __restrict__ ef, float* __restrict__ out) {
    int ns = g_nspill;                  // normally 0
    for (int i = threadIdx.x; i < ns; i += blockDim.x) {
        int4 sp = g_spill[i];
        const float* yrow = g_y + (size_t)sp.x * NF;
        const float4* e4 = (const float4*)(ef + (size_t)sp.y * ED);
        float4 ea = e4[0], eb = e4[1];
        float ev[8] = {ea.x, ea.y, ea.z, ea.w, eb.x, eb.y, eb.z, eb.w};
        float* op = out + (size_t)sp.z * (ED * NF);
        for (int k = 0; k < ED; k++)
            for (int o = 0; o < NF; o++)
                atomicAdd(&op[k * NF + o], ev[k] * yrow[o]);
    }
    __syncthreads();
    if (threadIdx.x == 0) g_nspill = 0;
}

// ---------------- launch ----------------

extern "C" void kernel_launch(void* const* d_in, const int* in_sizes, int n_in,
                              void* d_out, int out_size) {
    const float* node_feat = (const float*)d_in[0];
    const float* edge_feat = (const float*)d_in[1];
    const float* W         = (const float*)d_in[2];
    const float* b         = (const float*)d_in[3];
    const int*   src       = (const int*)d_in[4];
    const int*   dst       = (const int*)d_in[5];

    int N = in_sizes[0] / NF;     // 50000
    int E = in_sizes[4];          // 800000

    // Side stream for the (X,W)-only GEMM; event fork/join is capture-legal.
    cudaStream_t s2;
    cudaStreamCreateWithFlags(&s2, cudaStreamNonBlocking);
    cudaEvent_t evF, evJ;
    cudaEventCreateWithFlags(&evF, cudaEventDisableTiming);
    cudaEventCreateWithFlags(&evJ, cudaEventDisableTiming);

    cudaEventRecord(evF, 0);
    cudaStreamWaitEvent(s2, evF, 0);

    k_ygemm  <<<(N + 63) / 64, 256, 0, s2>>>(node_feat, W, N);        // hidden
    cudaEventRecord(evJ, s2);
    k_scatter<<<(E + 255) / 256, 256>>>(src, dst, E);                 // only build pass
    cudaStreamWaitEvent(0, evJ, 0);
    k_main   <<<(N + 3) / 4, 256>>>(edge_feat, b, (float*)d_out, N);
    k_spill  <<<1, 256>>>(edge_feat, (float*)d_out);
}

// round 13
// speedup vs baseline: 1.4198x; 1.4198x over previous
#include <cuda_runtime.h>

// EfConv: out[n, k*64+o] = sum_{e: dst_e=n} ef[e,k] * (node_feat[src_e] . W[o]) + b[o]
// y = X @ W^T first (side stream). Fixed-capacity buckets (128/node); build is
// one scatter pass; spill list guarantees correctness for any degree.
// R13: revert k_main to R11 warp-per-node form (R12's o-split doubled gather
// traffic -> regression). Add cache hints: out stores + rec writes evict-first
// (__stcs), bucket staging streaming (__ldcs) so y/ef stay L2-resident.

#define MAXN 50000
#define MAXE 800000
#define NF 64
#define ED 8
#define CAP 128                  // bucket slots per node

typedef unsigned long long u64;

__device__ int   g_cnt[MAXN];        // zero at load; re-zeroed by k_main epilogue
__device__ int   g_nspill;           // re-zeroed by k_spill
__device__ int4  g_spill[MAXE];      // (src, eid, dst, 0) overflow edges
__device__ __align__(16) int2 g_rec[(size_t)MAXN * CAP];   // buckets
__device__ float g_y[(size_t)(MAXN + 1) * NF];    // row MAXN stays all-zero (pad target)

// ---------------- packed f32x2 helpers ----------------
__device__ __forceinline__ void ffma2(u64 &d, u64 a, u64 b) {
    asm("fma.rn.f32x2 %0, %1, %2, %0;" : "+l"(d) : "l"(a), "l"(b));
}
__device__ __forceinline__ u64 pack2(float lo, float hi) {
    u64 r;
    asm("mov.b64 %0, {%1, %2};" : "=l"(r) : "f"(lo), "f"(hi));
    return r;
}
__device__ __forceinline__ void unpack2(float &lo, float &hi, u64 v) {
    asm("mov.b64 {%0, %1}, %2;" : "=f"(lo), "=f"(hi) : "l"(v));
}

// ---------------- scatter: the ONLY build pass ----------------
__global__ void k_scatter(const int* __restrict__ src, const int* __restrict__ dst, int E) {
    int t = blockIdx.x * blockDim.x + threadIdx.x;
    if (t >= E) return;
    int d = dst[t];
    int s = src[t];
    int pos = atomicAdd(&g_cnt[d], 1);
    if (pos < CAP) {
        __stcs(&g_rec[(size_t)d * CAP + pos], make_int2(s, t));   // evict-first
    } else {
        int sp = atomicAdd(&g_nspill, 1);
        g_spill[sp] = make_int4(s, t, d, 0);
    }
}

// ---------------- y = X @ W^T : 64 nodes/block, 4 nodes/thread ----------------
__global__ void __launch_bounds__(256) k_ygemm(const float* __restrict__ X,
                                               const float* __restrict__ W, int N) {
    __shared__ float WsT[NF * 68];
    __shared__ float xs[64][NF];
    int t = threadIdx.x;
    int base = blockIdx.x * 64;

    #pragma unroll
    for (int k = 0; k < 16; k++) {
        int idx = t + k * 256;
        int o = idx >> 6, i = idx & 63;
        WsT[i * 68 + o] = W[idx];
    }
    #pragma unroll
    for (int k = 0; k < 4; k++) {
        int idx = t + k * 256;
        int ln = idx >> 4, q = idx & 15;
        int n = base + ln;
        float4 v = (n < N) ? ((const float4*)(X + (size_t)n * NF))[q]
                           : make_float4(0.f, 0.f, 0.f, 0.f);
        ((float4*)&xs[ln][0])[q] = v;
    }
    __syncthreads();

    int o4 = (t & 15) * 4;
    int slot = t >> 4;
    float4 a0 = make_float4(0.f, 0.f, 0.f, 0.f);
    float4 a1 = a0, a2 = a0, a3 = a0;
    #pragma unroll 8
    for (int i = 0; i < NF; i++) {
        float4 w = *(const float4*)&WsT[i * 68 + o4];
        float x0 = xs[slot][i];
        float x1 = xs[slot + 16][i];
        float x2 = xs[slot + 32][i];
        float x3 = xs[slot + 48][i];
        a0.x += w.x * x0; a0.y += w.y * x0; a0.z += w.z * x0; a0.w += w.w * x0;
        a1.x += w.x * x1; a1.y += w.y * x1; a1.z += w.z * x1; a1.w += w.w * x1;
        a2.x += w.x * x2; a2.y += w.y * x2; a2.z += w.z * x2; a2.w += w.w * x2;
        a3.x += w.x * x3; a3.y += w.y * x3; a3.z += w.z * x3; a3.w += w.w * x3;
    }
    int n0 = base + slot;
    if (n0 < N)      *(float4*)(g_y + (size_t)n0 * NF + o4) = a0;
    if (n0 + 16 < N) *(float4*)(g_y + (size_t)(n0 + 16) * NF + o4) = a1;
    if (n0 + 32 < N) *(float4*)(g_y + (size_t)(n0 + 32) * NF + o4) = a2;
    if (n0 + 48 < N) *(float4*)(g_y + (size_t)(n0 + 48) * NF + o4) = a3;
}

// ---------------- main: warp-per-node, bucket staged in smem ----------------
__device__ __forceinline__ void edge2(u64 (&acc)[8], float4 ea, float4 eb, float2 yv) {
    u64 yx  = pack2(yv.x, yv.x);
    u64 yy  = pack2(yv.y, yv.y);
    u64 e01 = pack2(ea.x, ea.y);
    u64 e23 = pack2(ea.z, ea.w);
    u64 e45 = pack2(eb.x, eb.y);
    u64 e67 = pack2(eb.z, eb.w);
    ffma2(acc[0], e01, yx); ffma2(acc[1], e01, yy);
    ffma2(acc[2], e23, yx); ffma2(acc[3], e23, yy);
    ffma2(acc[4], e45, yx); ffma2(acc[5], e45, yy);
    ffma2(acc[6], e67, yx); ffma2(acc[7], e67, yy);
}

__device__ __forceinline__ void batch8(u64 (&acc)[8], const float* __restrict__ ef,
                                       const float* yb, int4 r01, int4 r23,
                                       int4 r45, int4 r67) {
    float2 y0 = *(const float2*)(yb + (size_t)r01.x * NF);
    float2 y1 = *(const float2*)(yb + (size_t)r01.z * NF);
    float2 y2 = *(const float2*)(yb + (size_t)r23.x * NF);
    float2 y3 = *(const float2*)(yb + (size_t)r23.z * NF);
    float2 y4 = *(const float2*)(yb + (size_t)r45.x * NF);
    float2 y5 = *(const float2*)(yb + (size_t)r45.z * NF);
    float2 y6 = *(const float2*)(yb + (size_t)r67.x * NF);
    float2 y7 = *(const float2*)(yb + (size_t)r67.z * NF);
    const float4* e0 = (const float4*)(ef + (size_t)r01.y * ED);
    const float4* e1 = (const float4*)(ef + (size_t)r01.w * ED);
    const float4* e2 = (const float4*)(ef + (size_t)r23.y * ED);
    const float4* e3 = (const float4*)(ef + (size_t)r23.w * ED);
    const float4* e4 = (const float4*)(ef + (size_t)r45.y * ED);
    const float4* e5 = (const float4*)(ef + (size_t)r45.w * ED);
    const float4* e6 = (const float4*)(ef + (size_t)r67.y * ED);
    const float4* e7 = (const float4*)(ef + (size_t)r67.w * ED);
    edge2(acc, e0[0], e0[1], y0);
    edge2(acc, e1[0], e1[1], y1);
    edge2(acc, e2[0], e2[1], y2);
    edge2(acc, e3[0], e3[1], y3);
    edge2(acc, e4[0], e4[1], y4);
    edge2(acc, e5[0], e5[1], y5);
    edge2(acc, e6[0], e6[1], y6);
    edge2(acc, e7[0], e7[1], y7);
}

__global__ void __launch_bounds__(256, 4) k_main(const float* __restrict__ ef,
                                                 const float* __restrict__ bvec,
                                                 float* __restrict__ out, int N) {
    __shared__ __align__(16) int2 srec[8][CAP];
    int wid = threadIdx.x >> 5;
    int lane = threadIdx.x & 31;
    int w = blockIdx.x * 8 + wid;
    bool live = (w < N);

    if (live) {
        float2 bb = *(const float2*)(bvec + lane * 2);
        int cnt = g_cnt[w];
        if (cnt > CAP) cnt = CAP;          // overflow edges handled by k_spill
        const int2* bucket = g_rec + (size_t)w * CAP;

        // stage bucket (coalesced 256B streaming loads)
        #pragma unroll
        for (int k = 0; k < CAP / 32; k++) {
            int idx = lane + k * 32;
            if (idx < cnt) srec[wid][idx] = __ldcs(&bucket[idx]);
        }
        // synthesize pad records up to multiple of 8 (src=N -> zero y row)
        int cnt8 = (cnt + 7) & ~7;
        if (lane < cnt8 - cnt) srec[wid][cnt + lane] = make_int2(N, 0);
        __syncwarp();

        u64 acc[8];
        #pragma unroll
        for (int a = 0; a < 8; a++) acc[a] = 0ull;

        const float* yb = g_y + lane * 2;

        for (int j = 0; j < cnt8; j += 8) {
            const int4* rp = (const int4*)&srec[wid][j];   // broadcast LDS
            batch8(acc, ef, yb, rp[0], rp[1], rp[2], rp[3]);
        }

        float* op = out + (size_t)w * (ED * NF);
        #pragma unroll
        for (int p = 0; p < 4; p++) {
            float xk0, xk1, yk0, yk1;
            unpack2(xk0, xk1, acc[2 * p]);
            unpack2(yk0, yk1, acc[2 * p + 1]);
            float2 v0, v1;
            v0.x = xk0 + bb.x;  v0.y = yk0 + bb.y;
            v1.x = xk1 + bb.x;  v1.y = yk1 + bb.y;
            __stcs((float2*)(op + (2 * p) * NF + lane * 2), v0);      // evict-first
            __stcs((float2*)(op + (2 * p + 1) * NF + lane * 2), v1);
        }
    }

    // reset counters for the NEXT invocation (after all warps in block read theirs)
    __syncthreads();
    if (threadIdx.x < 8) {
        int n2 = blockIdx.x * 8 + threadIdx.x;
        if (n2 < N) g_cnt[n2] = 0;
    }
}

// ---------------- spill fixup (normally empty) + nspill reset ----------------
__global__ void k_spill(const float* __restrict__ ef, float* __restrict__ out) {
    int ns = g_nspill;                  // normally 0
    for (int i = threadIdx.x; i < ns; i += blockDim.x) {
        int4 sp = g_spill[i];
        const float* yrow = g_y + (size_t)sp.x * NF;
        const float4* e4 = (const float4*)(ef + (size_t)sp.y * ED);
        float4 ea = e4[0], eb = e4[1];
        float ev[8] = {ea.x, ea.y, ea.z, ea.w, eb.x, eb.y, eb.z, eb.w};
        float* op = out + (size_t)sp.z * (ED * NF);
        for (int k = 0; k < ED; k++)
            for (int o = 0; o < NF; o++)
                atomicAdd(&op[k * NF + o], ev[k] * yrow[o]);
    }
    __syncthreads();
    if (threadIdx.x == 0) g_nspill = 0;
}

// ---------------- launch ----------------

extern "C" void kernel_launch(void* const* d_in, const int* in_sizes, int n_in,
                              void* d_out, int out_size) {
    const float* node_feat = (const float*)d_in[0];
    const float* edge_feat = (const float*)d_in[1];
    const float* W         = (const float*)d_in[2];
    const float* b         = (const float*)d_in[3];
    const int*   src       = (const int*)d_in[4];
    const int*   dst       = (const int*)d_in[5];

    int N = in_sizes[0] / NF;     // 50000
    int E = in_sizes[4];          // 800000

    // Side stream for the (X,W)-only GEMM; event fork/join is capture-legal.
    cudaStream_t s2;
    cudaStreamCreateWithFlags(&s2, cudaStreamNonBlocking);
    cudaEvent_t evF, evJ;
    cudaEventCreateWithFlags(&evF, cudaEventDisableTiming);
    cudaEventCreateWithFlags(&evJ, cudaEventDisableTiming);

    cudaEventRecord(evF, 0);
    cudaStreamWaitEvent(s2, evF, 0);

    k_ygemm  <<<(N + 63) / 64, 256, 0, s2>>>(node_feat, W, N);        // hidden
    cudaEventRecord(evJ, s2);
    k_scatter<<<(E + 255) / 256, 256>>>(src, dst, E);                 // only build pass
    cudaStreamWaitEvent(0, evJ, 0);
    k_main   <<<(N + 7) / 8, 256>>>(edge_feat, b, (float*)d_out, N);  // slot 3
    k_spill  <<<1, 256>>>(edge_feat, (float*)d_out);
}